// round 15
// baseline (speedup 1.0000x reference)
#include <cuda_runtime.h>
#include <cuda_fp16.h>
#include <cstdint>
#include <cstddef>

#define BATCH 8
#define CH 64
#define HH 256
#define WW 256
#define MM 12
#define KXM 24
#define NLAYERS 4
#define FCH 128
#define PADHh 264

// ---------------- device scratch ----------------
__device__ uint4 g_h4[BATCH*HH*HH*8];          // fp16 A-frag image, 2048 uint4/block
__device__ float g_Fy[BATCH*MM*CH*HH*2];       // [b][ky][c][x] float2
__device__ float g_E [BATCH*HH*CH*KXM];        // [b][x][o][ke]
// fp16 fragment tables (m16n8k16)
__device__ uint2 g_PWFh[NLAYERS*1024];         // pw B-frags
__device__ uint2 g_FC1Fh[2048];                // fc1 B-frags
__device__ uint4 g_TYFh[1024];                 // TYinv A-frags (pad k>=24 -> 0)
__device__ uint2 g_TYBHh[16*3*32];             // fwd y-DFT B-frags (fp16)
// tf32 tables (k_spec)
__device__ float g_F1A[64*3*32*4];             // A-frags fwd x-DFT
__device__ float g_F2B[6*64*32*2];             // B-frags inv x-DFT (/65536)
__device__ float g_WMIX[NLAYERS*MM*KXM*CH*CH*2];

__device__ __forceinline__ float gelu_f(float v){
    float z = fabsf(v)*0.70710678118654752f;
    float t = __fdividef(1.0f, fmaf(0.3275911f, z, 1.0f));
    float p = fmaf(1.061405429f, t, -1.453152027f);
    p = fmaf(p, t, 1.421413741f);
    p = fmaf(p, t, -0.284496736f);
    p = fmaf(p, t, 0.254829592f);
    p *= t;
    float e = __expf(-z*z);
    return v * (0.5f*(1.0f + copysignf(fmaf(-p, e, 1.0f), v)));
}
__device__ __forceinline__ float f2tf32(float x){
    uint32_t r; asm("cvt.rna.tf32.f32 %0, %1;" : "=r"(r) : "f"(x));
    return __uint_as_float(r);
}
__device__ __forceinline__ void mma_tf32(float& d0,float& d1,float& d2,float& d3,
                                         float a0,float a1,float a2,float a3,
                                         float b0,float b1){
    asm volatile("mma.sync.aligned.m16n8k8.row.col.f32.tf32.tf32.f32 "
        "{%0,%1,%2,%3}, {%4,%5,%6,%7}, {%8,%9}, {%0,%1,%2,%3};"
        : "+f"(d0),"+f"(d1),"+f"(d2),"+f"(d3)
        : "r"(__float_as_uint(a0)),"r"(__float_as_uint(a1)),
          "r"(__float_as_uint(a2)),"r"(__float_as_uint(a3)),
          "r"(__float_as_uint(b0)),"r"(__float_as_uint(b1)));
}
__device__ __forceinline__ void mma_f16(float& d0,float& d1,float& d2,float& d3,
                                        uint4 a, uint2 b){
    asm volatile("mma.sync.aligned.m16n8k16.row.col.f32.f16.f16.f32 "
        "{%0,%1,%2,%3}, {%4,%5,%6,%7}, {%8,%9}, {%0,%1,%2,%3};"
        : "+f"(d0),"+f"(d1),"+f"(d2),"+f"(d3)
        : "r"(a.x),"r"(a.y),"r"(a.z),"r"(a.w),"r"(b.x),"r"(b.y));
}
__device__ __forceinline__ unsigned short h_us(float v){
    __half h = __float2half_rn(v);
    return *(unsigned short*)&h;
}

// pack fp16 HSh tile [k=i][y] -> fp16 A-frag image item u (0..2047)
__device__ __forceinline__ void pack_row_h(const __half* __restrict__ HSh,
                                           uint4* __restrict__ dst, int u){
    int row=u>>5, lane=u&31;
    int kk=row>>4, yt=row&15, g=lane>>2, t4=lane&3;
    uint32_t w[4];
#pragma unroll
    for (int r=0;r<4;r++){
        int kh=r>>1, hf=r&1;
        int y = yt*16 + g + 8*hf;
        int k0 = kk*16 + kh*8 + t4*2;
        __half2 hh = __halves2half2(HSh[k0*PADHh+y], HSh[(k0+1)*PADHh+y]);
        w[r] = *(uint32_t*)&hh;
    }
    dst[u] = make_uint4(w[0],w[1],w[2],w[3]);
}

// ---------------- fused y-DFT epilogue (fp16 m16n8k16, 4 warps) ----------------
__device__ __forceinline__ void dft_epi_h(const __half* __restrict__ HSh, int b, int xr,
                                          int warp, int lane){
    int g = lane>>2, t4 = lane&3;
    int mt = warp;
    float c[3][4];
#pragma unroll
    for (int nt=0;nt<3;nt++)
#pragma unroll
        for (int r=0;r<4;r++) c[nt][r]=0.f;
#pragma unroll
    for (int kk=0; kk<16; kk++){
        const __half* r0 = HSh + (mt*16+g)*PADHh + kk*16 + t4*2;
        const __half* r1 = r0 + 8*PADHh;
        uint4 af;
        af.x = *(const uint32_t*)r0;
        af.y = *(const uint32_t*)r1;
        af.z = *(const uint32_t*)(r0+8);
        af.w = *(const uint32_t*)(r1+8);
#pragma unroll
        for (int nt=0;nt<3;nt++){
            uint2 bf = __ldg(g_TYBHh + (kk*3+nt)*32 + lane);
            mma_f16(c[nt][0],c[nt][1],c[nt][2],c[nt][3], af, bf);
        }
    }
    float2* Fy2 = (float2*)g_Fy;
    int o = mt*16+g;
#pragma unroll
    for (int nt=0;nt<3;nt++){
        int ky = nt*4+t4;
        size_t base = (((size_t)(b*MM+ky)*CH + o)<<8) + xr;
        Fy2[base]          = make_float2(c[nt][0], c[nt][1]);
        Fy2[base + (8<<8)] = make_float2(c[nt][2], c[nt][3]);
    }
}

// ---------------- constant prep ----------------
__global__ void k_frw(const float* __restrict__ pw_w, const float* __restrict__ fc1w){
    int t = blockIdx.x*blockDim.x + threadIdx.x;
    if (t < 16384){                                  // pw fp16 B-frags
        int layer = t>>12; int d = t&4095;
        int kk=d>>10, ot=(d>>7)&7, lane=(d>>2)&31, kh=(d>>1)&1, hi=d&1;
        int t4=lane&3, g=lane>>2;
        int k = kk*16 + kh*8 + t4*2 + hi;
        int o = ot*8 + g;
        ((unsigned short*)g_PWFh)[t] = h_us(pw_w[(layer*CH+o)*CH + k]);
    } else if (t < 24576){                           // fc1 fp16 B-frags
        int d = t - 16384;
        int kk=d>>11, ot=(d>>7)&15, lane=(d>>2)&31, kh=(d>>1)&1, hi=d&1;
        int t4=lane&3, g=lane>>2;
        int k = kk*16 + kh*8 + t4*2 + hi;
        int f = ot*8 + g;
        ((unsigned short*)g_FC1Fh)[d] = h_us(fc1w[f*CH + k]);
    } else if (t < 32768){                           // TYinv fp16 A-frags (+zero pad)
        int u = t - 24576;
        int hi=u&1, r=(u>>1)&3, lane=(u>>3)&31, yt=(u>>8)&15, kk=u>>12;
        int kh=r>>1, hf=r&1, g=lane>>2, t4=lane&3;
        int y = yt*16 + g + 8*hf;
        int relk = kk*16 + kh*8 + t4*2 + hi;
        float v = 0.f;
        if (relk < 24){
            int ky2 = relk>>1;
            int r2 = (ky2*y) & 255;
            double s2,c2; sincospi(2.0*r2/256.0, &s2, &c2);
            if ((relk&1)==0) v = (ky2==0)? 1.0f : 2.0f*(float)c2;
            else             v = (ky2==0)? 0.0f : -2.0f*(float)s2;
        }
        ((unsigned short*)g_TYFh)[u] = h_us(v);
    } else if (t < 38912){                           // fwd y-DFT fp16 B-frags
        int u = t - 32768;
        int hi = u&1, kh=(u>>1)&1, lane=(u>>2)&31;
        int nt = (u>>7)%3, kk = u/384;
        int t4=lane&3, g=lane>>2;
        int y = kk*16 + kh*8 + t4*2 + hi;
        int n = nt*8 + g;
        int kmode = n>>1;
        int rr = (kmode*y)&255;
        double s,c; sincospi(2.0*rr/256.0, &s, &c);
        float v = (n&1)? (float)(-s) : (float)c;
        ((unsigned short*)g_TYBHh)[(((kk*3+nt)*32+lane)*2+kh)*2+hi] = h_us(v);
    } else if (t < 63488){                           // fwd x-DFT tf32 A-frags
        int u = t - 38912;
        int slot = u&3, lane = (u>>2)&31, mt = (u>>7)%3, kk = u/384;
        int g = lane>>2, t4 = lane&3, hf = slot&1, kh = slot>>1;
        int m = mt*16 + g + 8*hf;
        int k = kk*8 + t4 + 4*kh;
        int j = m>>1, ri = m&1;
        int x = k>>1, xi = k&1;
        int keff = (j<12)? j : (j-24);
        int rr = ((keff*x)%256 + 256) & 255;
        double s,c; sincospi(2.0*rr/256.0, &s, &c);
        float v = (ri==0) ? ((xi==0)? (float)c : (float)s)
                          : ((xi==0)? (float)(-s) : (float)c);
        g_F1A[u] = f2tf32(v);
    } else if (t < 88064){                           // inv x-DFT tf32 B-frags
        int u = t - 63488;
        int kh = u&1, lane = (u>>1)&31, nt = (u>>6)&63, kk = u>>12;
        int g = lane>>2, t4 = lane&3;
        int k = kk*8 + t4 + 4*kh;
        int j = k>>1, ri = k&1;
        int n = nt*8 + g;
        int x = n>>1, xi = n&1;
        int keff = (j<12)? j : (j-24);
        int rr = ((keff*x)%256 + 256) & 255;
        double s,c; sincospi(2.0*rr/256.0, &s, &c);
        float v = (ri==0) ? ((xi==0)? (float)c : (float)s)
                          : ((xi==0)? (float)(-s) : (float)c);
        g_F2B[u] = f2tf32(v * (1.0f/65536.0f));
    }
}

// ---------------- weight transpose via smem ----------------
#define WMIX_SMEM (2*64*145*4)
__global__ void __launch_bounds__(256) k_wmix(const float* __restrict__ w1,
                                              const float* __restrict__ w2){
    extern __shared__ float sm[];
    float* sre = sm;
    float* sim = sm + 64*145;
    int which = blockIdx.x & 1;
    int li = blockIdx.x >> 1;
    const float2* src = ((const float2*)(which? w2 : w1)) + (size_t)li*9216;
    for (int t=threadIdx.x; t<9216; t+=256){
        float2 v = src[t];
        int o = t/144, jk = t - o*144;
        sre[o*145+jk] = v.x;
        sim[o*145+jk] = v.y;
    }
    __syncthreads();
    int l = li>>6, i = li&63;
    int warp = threadIdx.x>>5, lane = threadIdx.x&31;
    for (int jk=warp; jk<144; jk+=8){
        int jm = jk/12, ky = jk - jm*12;
        int j = jm + (which? 12:0);
        float2* dst = ((float2*)g_WMIX) + ((size_t)((l*12+ky)*24 + j))*4096 + i*64;
        dst[lane]    = make_float2(sre[lane*145+jk],      sim[lane*145+jk]);
        dst[lane+32] = make_float2(sre[(lane+32)*145+jk], sim[(lane+32)*145+jk]);
    }
}

// ---------------- lift (fc0) -> Fy (fp16 tile + fp16 epi) ----------------
#define LIFT_SMEM ((8448 + 256)*4)
__global__ void __launch_bounds__(256) k_lift_fy(const float* __restrict__ x,
                                                 const float* __restrict__ fw,
                                                 const float* __restrict__ fb){
    extern __shared__ float smf[];
    __half* HSh = (__half*)smf;             // [64][PADHh]
    float* xs = smf + 8448;
    int b = blockIdx.x>>8, xr = blockIdx.x&255;
    int tid = threadIdx.x;
    if (tid < 64)
        ((float4*)xs)[tid] = ((const float4*)(x + (((size_t)b)<<16) + (xr<<8)))[tid];
    __syncthreads();
    float gx = xr*(1.0f/255.0f);
    for (int t=tid; t<CH*64; t+=256){
        int i=t>>6, q=t&63;
        float w0=__ldg(fw+i*3), w1=__ldg(fw+i*3+1), w2=__ldg(fw+i*3+2);
        float base = w1*gx + __ldg(fb+i);
        float v0 = w0*xs[q*4  ] + w2*((q*4  )*(1.0f/255.0f)) + base;
        float v1 = w0*xs[q*4+1] + w2*((q*4+1)*(1.0f/255.0f)) + base;
        float v2 = w0*xs[q*4+2] + w2*((q*4+2)*(1.0f/255.0f)) + base;
        float v3 = w0*xs[q*4+3] + w2*((q*4+3)*(1.0f/255.0f)) + base;
        *(__half2*)&HSh[i*PADHh + q*4]     = __floats2half2_rn(v0, v1);
        *(__half2*)&HSh[i*PADHh + q*4 + 2] = __floats2half2_rn(v2, v3);
    }
    __syncthreads();
    if (tid < 128) dft_epi_h(HSh, b, xr, tid>>5, tid&31);
}

// ---------------- K-spec (tf32, dual-accumulator GEMM1) ----------------
#define BF1_F2 (64*8*32)
#define G_STRIDE 65
#define G_F (48*G_STRIDE)
#define AF2_F (6*4*32*4)
#define PB1_F (48*128)
#define SPEC_SMEM ((BF1_F2*2 + G_F + AF2_F + PB1_F)*4)

__global__ void __launch_bounds__(512,1)
k_spec(int layer){
    extern __shared__ float sm[];
    float* BF1f = sm;
    float* Gs   = sm + 2*BF1_F2;
    float* AF2  = Gs + G_F;
    float* PB   = AF2 + AF2_F;
    int b = blockIdx.x/12, ky = blockIdx.x%12;
    int tid = threadIdx.x, lane = tid&31, warp = tid>>5;

    const float2* fy = ((const float2*)g_Fy) + (((size_t)(b*MM+ky))<<14);
    for (int t=tid; t<64*256; t+=512){
        int c = t>>8, x = t&255;
        float2 v = fy[t];
        int nt=c>>3, g=c&7;
        int k0=2*x;
        int kk=k0>>3, t4=k0&3, kh=(k0>>2)&1;
        int base = ((kk*8+nt)<<5);
        BF1f[(base + ((g<<2)|t4    ))*2 + kh] = f2tf32(v.x);
        BF1f[(base + ((g<<2)|(t4+1)))*2 + kh] = f2tf32(v.y);
    }
    __syncthreads();
    {   // GEMM1 split-k, DUAL accumulator chains (16-deep each)
        const float4* A4 = (const float4*)g_F1A;
        const float2* B2 = (const float2*)BF1f;
        for (int u=warp; u<48; u+=16){
            int tile = u%24, khalf = u/24;
            int mt = tile%3, nt = tile/3;
            float c0=0.f,c1=0.f,c2=0.f,c3=0.f;
            float d0=0.f,d1=0.f,d2=0.f,d3=0.f;
            int kb = khalf*32;
#pragma unroll 8
            for (int kk=kb; kk<kb+16; kk++){
                float4 a0 = __ldg(A4 + ((kk*3+mt)<<5)+lane);
                float2 b0 = B2[((kk*8+nt)<<5)+lane];
                float4 a1 = __ldg(A4 + (((kk+16)*3+mt)<<5)+lane);
                float2 b1 = B2[(((kk+16)*8+nt)<<5)+lane];
                mma_tf32(c0,c1,c2,c3, a0.x,a0.y,a0.z,a0.w, b0.x,b0.y);
                mma_tf32(d0,d1,d2,d3, a1.x,a1.y,a1.z,a1.w, b1.x,b1.y);
            }
            float* pb = PB + u*128 + lane*4;
            pb[0]=c0+d0; pb[1]=c1+d1; pb[2]=c2+d2; pb[3]=c3+d3;
        }
    }
    __syncthreads();
    for (int t=tid; t<3072; t+=512){
        int row = t>>6, col = t&63;
        int mt = row>>4, rr = row&15, g = rr&7, hi = rr>>3;
        int nt = col>>3, cc = col&7, t4 = cc>>1, r0 = (hi<<1)|(cc&1);
        int lidx = g*4+t4;
        int tile = nt*3+mt;
        Gs[row*G_STRIDE+col] = PB[tile*128 + lidx*4 + r0] + PB[(tile+24)*128 + lidx*4 + r0];
    }
    __syncthreads();
    {   // mode mix (fp32 scalar)
        const float2* WM = ((const float2*)g_WMIX) + ((size_t)((layer*12+ky)*24))*4096;
#pragma unroll
        for (int r=0; r<3; r++){
            int item = tid + 512*r;
            int j = item>>6, o = item&63;
            const float2* wrow = WM + j*4096 + o;
            const float* Gr = Gs + (2*j)*G_STRIDE;
            const float* Gi = Gs + (2*j+1)*G_STRIDE;
            float ar0=0.f, ai0=0.f, ar1=0.f, ai1=0.f;
#pragma unroll 8
            for (int i=0;i<64;i+=2){
                float2 wv0 = __ldg(wrow + i*64);
                float2 wv1 = __ldg(wrow + (i+1)*64);
                float g0r = Gr[i],   g0i = Gi[i];
                float g1r = Gr[i+1], g1i = Gi[i+1];
                ar0 += g0r*wv0.x - g0i*wv0.y;
                ai0 += g0r*wv0.y + g0i*wv0.x;
                ar1 += g1r*wv1.x - g1i*wv1.y;
                ai1 += g1r*wv1.y + g1i*wv1.x;
            }
            float ar = ar0+ar1, ai = ai0+ai1;
            int mt=o>>4, half=(o>>3)&1, gg=o&7;
            int k0=2*j;
            int kk=k0>>3, t40=k0&3, kh=(k0>>2)&1;
            int base = ((kk*4+mt)<<5);
            AF2[(base + ((gg<<2)|t40    ))*4 + ((kh<<1)|half)] = f2tf32(ar);
            AF2[(base + ((gg<<2)|(t40+1)))*4 + ((kh<<1)|half)] = f2tf32(ai);
        }
    }
    __syncthreads();
    {   // GEMM2 tf32 -> E
        int mt = warp&3, ntb = (warp>>2)<<4;
        float4 Areg[6];
#pragma unroll
        for (int kk=0;kk<6;kk++)
            Areg[kk] = ((const float4*)AF2)[((kk*4+mt)<<5)+lane];
        int g=lane>>2, t4=lane&3;
        const float2* B2 = (const float2*)g_F2B;
        float2* E2 = (float2*)g_E;
        for (int ni=0;ni<16;ni++){
            int nt = ntb+ni;
            float c0=0.f,c1=0.f,c2=0.f,c3=0.f;
#pragma unroll
            for (int kk=0;kk<6;kk++){
                float2 bf = __ldg(B2 + ((kk*64+nt)<<5)+lane);
                mma_tf32(c0,c1,c2,c3, Areg[kk].x,Areg[kk].y,Areg[kk].z,Areg[kk].w, bf.x,bf.y);
            }
            int x = nt*4+t4, o = mt*16+g;
            E2[((size_t)(b*HH+x)*CH + o  )*12 + ky] = make_float2(c0,c1);
            E2[((size_t)(b*HH+x)*CH + o+8)*12 + ky] = make_float2(c2,c3);
        }
    }
}

// ---------------- K5: fused layer (fp16 GEMMs + fp16 HSh + fp16 epi) ----------------
#define K5_SMEM (18240*4)

__global__ void __launch_bounds__(256,2)
k_layer(const float* __restrict__ xg, const float* __restrict__ fc0w,
        const float* __restrict__ fc0b, const float* __restrict__ pw_b,
        const float* __restrict__ fc1b, const float* __restrict__ fc2w,
        const float* __restrict__ fc2b, float* __restrict__ out, int layer){
    extern __shared__ float smf[];
    uint4* AFh = (uint4*)smf;               // 2048 uint4
    uint2* EF  = (uint2*)(smf + 8192);      // 512 uint2
    float* part= smf + 8192;                // head overlay
    __half* HSh = (__half*)(smf + 9216);    // [64][PADHh]
    float* bs  = smf + 17664;
    float* w0s = bs + 64;
    float* b0s = w0s + 192;
    float* xs  = b0s + 64;
    int b = blockIdx.x>>8, xr = blockIdx.x&255;
    int tid = threadIdx.x, lane = tid&31, warp = tid>>5;

    for (int t=tid; t<1024; t+=256) ((uint32_t*)EF)[t] = 0;
    if (tid<64) bs[tid] = pw_b[layer*CH+tid];
    if (layer==0){
        if (tid<192) w0s[tid] = fc0w[tid];
        if (tid<64)  b0s[tid] = fc0b[tid];
        if (tid<64)
            ((float4*)xs)[tid] = ((const float4*)(xg + (((size_t)b)<<16)+(xr<<8)))[tid];
    }
    __syncthreads();

    {   // E scatter -> fp16 B-frags
        const float* Eb = g_E + ((size_t)(b*HH+xr))*CH*24;
        unsigned short* EFh = (unsigned short*)EF;
        for (int t=tid; t<KXM*CH; t+=256){
            int o=t/24, ke=t%24;
            int kk=ke>>4, kin=ke&15, t4e=(kin>>1)&3, hi=kin&1, kh=kin>>3;
            int ot=o>>3, g=o&7;
            EFh[(((kk*8+ot)*32 + (g*4+t4e))*2 + kh)*2 + hi] = h_us(Eb[t]);
        }
    }
    if (layer==0){
        float gx = xr*(1.0f/255.0f);
        for (int t=tid; t<CH*64; t+=256){
            int i=t>>6, q=t&63;
            float w0=w0s[i*3], w1=w0s[i*3+1], w2=w0s[i*3+2];
            float base = w1*gx + b0s[i];
            float v0 = w0*xs[q*4  ] + w2*((q*4  )*(1.0f/255.0f)) + base;
            float v1 = w0*xs[q*4+1] + w2*((q*4+1)*(1.0f/255.0f)) + base;
            float v2 = w0*xs[q*4+2] + w2*((q*4+2)*(1.0f/255.0f)) + base;
            float v3 = w0*xs[q*4+3] + w2*((q*4+3)*(1.0f/255.0f)) + base;
            *(__half2*)&HSh[i*PADHh + q*4]     = __floats2half2_rn(v0, v1);
            *(__half2*)&HSh[i*PADHh + q*4 + 2] = __floats2half2_rn(v2, v3);
        }
        __syncthreads();
        for (int u=tid; u<2048; u+=256) pack_row_h(HSh, AFh, u);
    } else {
        const uint4* hg = g_h4 + ((size_t)blockIdx.x<<11);
        for (int t=tid; t<2048; t+=256) AFh[t] = hg[t];
    }
    __syncthreads();

    int wy = warp>>1, wo = warp&1;
    float c[4][4][4];
#pragma unroll
    for (int mi=0;mi<4;mi++)
#pragma unroll
        for (int ni=0;ni<4;ni++)
#pragma unroll
            for (int r=0;r<4;r++) c[mi][ni][r]=0.f;

    const uint2* PW = g_PWFh + layer*1024;
#pragma unroll
    for (int kk=0; kk<4; kk++){
        uint2 bf[4];
#pragma unroll
        for (int ni=0;ni<4;ni++)
            bf[ni] = __ldg(PW + (kk*8 + wo*4+ni)*32 + lane);
#pragma unroll
        for (int mi=0;mi<4;mi++){
            uint4 af = AFh[(kk*16 + wy*4+mi)*32 + lane];
#pragma unroll
            for (int ni=0;ni<4;ni++)
                mma_f16(c[mi][ni][0],c[mi][ni][1],c[mi][ni][2],c[mi][ni][3], af, bf[ni]);
        }
    }
#pragma unroll
    for (int kk=0; kk<2; kk++){
        uint2 bf[4];
#pragma unroll
        for (int ni=0;ni<4;ni++)
            bf[ni] = EF[(kk*8 + wo*4+ni)*32 + lane];
#pragma unroll
        for (int mi=0;mi<4;mi++){
            uint4 af = __ldg(g_TYFh + (kk*16 + wy*4+mi)*32 + lane);
#pragma unroll
            for (int ni=0;ni<4;ni++)
                mma_f16(c[mi][ni][0],c[mi][ni][1],c[mi][ni][2],c[mi][ni][3], af, bf[ni]);
        }
    }

    int g = lane>>2, t4 = lane&3;
    int dogelu = (layer < NLAYERS-1);
#pragma unroll
    for (int mi=0;mi<4;mi++){
#pragma unroll
        for (int ni=0;ni<4;ni++){
            int o = (wo*4+ni)*8 + 2*t4;
            float bb0 = bs[o], bb1 = bs[o+1];
            float v0 = c[mi][ni][0] + bb0;
            float v1 = c[mi][ni][1] + bb1;
            float v2 = c[mi][ni][2] + bb0;
            float v3 = c[mi][ni][3] + bb1;
            if (dogelu){ v0=gelu_f(v0); v1=gelu_f(v1); v2=gelu_f(v2); v3=gelu_f(v3); }
            c[mi][ni][0]=v0; c[mi][ni][1]=v1; c[mi][ni][2]=v2; c[mi][ni][3]=v3;
        }
    }

    if (layer < NLAYERS-1){
        __syncthreads();
#pragma unroll
        for (int mi=0;mi<4;mi++){
            int y = (wy*4+mi)*16 + g;
#pragma unroll
            for (int ni=0;ni<4;ni++){
                int o = (wo*4+ni)*8 + 2*t4;
                HSh[ o   *PADHh + y  ] = __float2half_rn(c[mi][ni][0]);
                HSh[(o+1)*PADHh + y  ] = __float2half_rn(c[mi][ni][1]);
                HSh[ o   *PADHh + y+8] = __float2half_rn(c[mi][ni][2]);
                HSh[(o+1)*PADHh + y+8] = __float2half_rn(c[mi][ni][3]);
            }
        }
        __syncthreads();
        if (warp < 4){
            dft_epi_h(HSh, b, xr, warp, lane);
        } else {
            uint4* hg = g_h4 + ((size_t)blockIdx.x<<11);
            for (int u=tid-128; u<2048; u+=128) pack_row_h(HSh, hg, u);
        }
        return;
    }

    // ---- layer 3: fused head (fp16) ----
    __syncthreads();
    {
        unsigned short* AH = (unsigned short*)AFh;
#pragma unroll
        for (int mi=0;mi<4;mi++){
#pragma unroll
            for (int ni=0;ni<4;ni++){
#pragma unroll
                for (int r=0;r<4;r++){
                    int o = (wo*4+ni)*8 + 2*t4 + (r&1);
                    int y = (wy*4+mi)*16 + g + ((r>>1)<<3);
                    int kk=o>>4, kin=o&15, t4n=(kin>>1)&3, hin=kin&1, khn=kin>>3;
                    int yt=y>>4, yin=y&15, gn=yin&7, halfn=yin>>3;
                    int reg = khn*2 + halfn;
                    AH[(((kk*16+yt)*32 + (gn*4+t4n))*4 + reg)*2 + hin] =
                        h_us(c[mi][ni][r]);
                }
            }
        }
    }
    __syncthreads();

    float s0[4] = {0.f,0.f,0.f,0.f}, s1[4] = {0.f,0.f,0.f,0.f};
#pragma unroll
    for (int p=0; p<2; p++){
#pragma unroll
        for (int mi=0;mi<4;mi++)
#pragma unroll
            for (int ni=0;ni<4;ni++)
#pragma unroll
                for (int r=0;r<4;r++) c[mi][ni][r]=0.f;
#pragma unroll
        for (int kk=0; kk<4; kk++){
            uint2 bf[4];
#pragma unroll
            for (int ni=0;ni<4;ni++)
                bf[ni] = __ldg(g_FC1Fh + (kk*16 + p*8 + wo*4+ni)*32 + lane);
#pragma unroll
            for (int mi=0;mi<4;mi++){
                uint4 af = AFh[(kk*16 + wy*4+mi)*32 + lane];
#pragma unroll
                for (int ni=0;ni<4;ni++)
                    mma_f16(c[mi][ni][0],c[mi][ni][1],c[mi][ni][2],c[mi][ni][3],
                            af, bf[ni]);
            }
        }
#pragma unroll
        for (int mi=0;mi<4;mi++){
#pragma unroll
            for (int ni=0;ni<4;ni++){
                int f = (p*8 + wo*4+ni)*8 + 2*t4;
                float ba = __ldg(fc1b+f), bb = __ldg(fc1b+f+1);
                float wa = __ldg(fc2w+f), wb = __ldg(fc2w+f+1);
                s0[mi] += gelu_f(c[mi][ni][0]+ba)*wa + gelu_f(c[mi][ni][1]+bb)*wb;
                s1[mi] += gelu_f(c[mi][ni][2]+ba)*wa + gelu_f(c[mi][ni][3]+bb)*wb;
            }
        }
    }
#pragma unroll
    for (int mi=0;mi<4;mi++){
        float a0 = s0[mi], a1 = s1[mi];
        a0 += __shfl_xor_sync(0xffffffffu, a0, 1);
        a0 += __shfl_xor_sync(0xffffffffu, a0, 2);
        a1 += __shfl_xor_sync(0xffffffffu, a1, 1);
        a1 += __shfl_xor_sync(0xffffffffu, a1, 2);
        if (t4==0){
            int y = (wy*4+mi)*16 + g;
            part[wo*WW + y]   = a0;
            part[wo*WW + y+8] = a1;
        }
    }
    __syncthreads();
    {
        int y = tid;
        float s = part[y] + part[WW+y] + __ldg(fc2b);
        out[(((size_t)b)<<16) + (xr<<8) + y] = s;
    }
}

// ---------------- launch ----------------
extern "C" void kernel_launch(void* const* d_in, const int* in_sizes, int n_in,
                              void* d_out, int out_size){
    (void)in_sizes; (void)n_in; (void)out_size;
    const float* x     = (const float*)d_in[0];
    const float* fc0_w = (const float*)d_in[1];
    const float* fc0_b = (const float*)d_in[2];
    const float* w1    = (const float*)d_in[3];
    const float* w2    = (const float*)d_in[4];
    const float* pw_w  = (const float*)d_in[5];
    const float* pw_b  = (const float*)d_in[6];
    const float* fc1_w = (const float*)d_in[7];
    const float* fc1_b = (const float*)d_in[8];
    const float* fc2_w = (const float*)d_in[9];
    const float* fc2_b = (const float*)d_in[10];
    float* out = (float*)d_out;

    cudaFuncSetAttribute(k_layer,   cudaFuncAttributeMaxDynamicSharedMemorySize, K5_SMEM);
    cudaFuncSetAttribute(k_spec,    cudaFuncAttributeMaxDynamicSharedMemorySize, SPEC_SMEM);
    cudaFuncSetAttribute(k_lift_fy, cudaFuncAttributeMaxDynamicSharedMemorySize, LIFT_SMEM);
    cudaFuncSetAttribute(k_wmix,    cudaFuncAttributeMaxDynamicSharedMemorySize, WMIX_SMEM);

    k_frw<<<344,256>>>(pw_w, fc1_w);
    k_wmix<<<512,256,WMIX_SMEM>>>(w1, w2);
    k_lift_fy<<<BATCH*HH,256,LIFT_SMEM>>>(x, fc0_w, fc0_b);
    for (int l=0; l<NLAYERS; l++){
        k_spec<<<BATCH*MM,512,SPEC_SMEM>>>(l);
        k_layer<<<BATCH*HH,256,K5_SMEM>>>(x, fc0_w, fc0_b, pw_b,
                                          fc1_b, fc2_w, fc2_b, out, l);
    }
}

// round 16
// speedup vs baseline: 1.0409x; 1.0409x over previous
#include <cuda_runtime.h>
#include <cuda_fp16.h>
#include <cstdint>
#include <cstddef>

#define BATCH 8
#define CH 64
#define HH 256
#define WW 256
#define MM 12
#define KXM 24
#define NLAYERS 4
#define FCH 128
#define PADHh 264

// ---------------- device scratch ----------------
__device__ uint4 g_h4[BATCH*HH*HH*8];          // fp16 A-frag image, 2048 uint4/block
__device__ float g_Fy[BATCH*MM*CH*HH*2];       // [b][ky][c][x] float2
__device__ float g_E [BATCH*HH*CH*KXM];        // [b][x][o][ke]
// fp16 fragment tables (m16n8k16)
__device__ uint2 g_PWFh[NLAYERS*1024];         // pw B-frags
__device__ uint2 g_FC1Fh[2048];                // fc1 B-frags
__device__ uint4 g_TYFh[1024];                 // TYinv A-frags (pad k>=24 -> 0)
__device__ uint2 g_TYBHh[16*3*32];             // fwd y-DFT B-frags (fp16)
__device__ uint4 g_F1Ah[3072];                 // fwd x-DFT A-frags (fp16, M=48,K=512)
// tf32 tables (k_spec tail)
__device__ float g_F2B[6*64*32*2];             // B-frags inv x-DFT (/65536)
__device__ float g_WMIX[NLAYERS*MM*KXM*CH*CH*2];

__device__ __forceinline__ float gelu_f(float v){
    float z = fabsf(v)*0.70710678118654752f;
    float t = __fdividef(1.0f, fmaf(0.3275911f, z, 1.0f));
    float p = fmaf(1.061405429f, t, -1.453152027f);
    p = fmaf(p, t, 1.421413741f);
    p = fmaf(p, t, -0.284496736f);
    p = fmaf(p, t, 0.254829592f);
    p *= t;
    float e = __expf(-z*z);
    return v * (0.5f*(1.0f + copysignf(fmaf(-p, e, 1.0f), v)));
}
__device__ __forceinline__ float f2tf32(float x){
    uint32_t r; asm("cvt.rna.tf32.f32 %0, %1;" : "=r"(r) : "f"(x));
    return __uint_as_float(r);
}
__device__ __forceinline__ void mma_tf32(float& d0,float& d1,float& d2,float& d3,
                                         float a0,float a1,float a2,float a3,
                                         float b0,float b1){
    asm volatile("mma.sync.aligned.m16n8k8.row.col.f32.tf32.tf32.f32 "
        "{%0,%1,%2,%3}, {%4,%5,%6,%7}, {%8,%9}, {%0,%1,%2,%3};"
        : "+f"(d0),"+f"(d1),"+f"(d2),"+f"(d3)
        : "r"(__float_as_uint(a0)),"r"(__float_as_uint(a1)),
          "r"(__float_as_uint(a2)),"r"(__float_as_uint(a3)),
          "r"(__float_as_uint(b0)),"r"(__float_as_uint(b1)));
}
__device__ __forceinline__ void mma_f16(float& d0,float& d1,float& d2,float& d3,
                                        uint4 a, uint2 b){
    asm volatile("mma.sync.aligned.m16n8k16.row.col.f32.f16.f16.f32 "
        "{%0,%1,%2,%3}, {%4,%5,%6,%7}, {%8,%9}, {%0,%1,%2,%3};"
        : "+f"(d0),"+f"(d1),"+f"(d2),"+f"(d3)
        : "r"(a.x),"r"(a.y),"r"(a.z),"r"(a.w),"r"(b.x),"r"(b.y));
}
__device__ __forceinline__ unsigned short h_us(float v){
    __half h = __float2half_rn(v);
    return *(unsigned short*)&h;
}
__device__ __forceinline__ uint32_t h2_u32(float a, float b){
    __half2 h = __floats2half2_rn(a, b);
    return *(uint32_t*)&h;
}

// pack fp16 HSh tile [k=i][y] -> fp16 A-frag image item u (0..2047)
__device__ __forceinline__ void pack_row_h(const __half* __restrict__ HSh,
                                           uint4* __restrict__ dst, int u){
    int row=u>>5, lane=u&31;
    int kk=row>>4, yt=row&15, g=lane>>2, t4=lane&3;
    uint32_t w[4];
#pragma unroll
    for (int r=0;r<4;r++){
        int kh=r>>1, hf=r&1;
        int y = yt*16 + g + 8*hf;
        int k0 = kk*16 + kh*8 + t4*2;
        __half2 hh = __halves2half2(HSh[k0*PADHh+y], HSh[(k0+1)*PADHh+y]);
        w[r] = *(uint32_t*)&hh;
    }
    dst[u] = make_uint4(w[0],w[1],w[2],w[3]);
}

// ---------------- fused y-DFT epilogue (fp16 m16n8k16, 4 warps) ----------------
__device__ __forceinline__ void dft_epi_h(const __half* __restrict__ HSh, int b, int xr,
                                          int warp, int lane){
    int g = lane>>2, t4 = lane&3;
    int mt = warp;
    float c[3][4];
#pragma unroll
    for (int nt=0;nt<3;nt++)
#pragma unroll
        for (int r=0;r<4;r++) c[nt][r]=0.f;
#pragma unroll
    for (int kk=0; kk<16; kk++){
        const __half* r0 = HSh + (mt*16+g)*PADHh + kk*16 + t4*2;
        const __half* r1 = r0 + 8*PADHh;
        uint4 af;
        af.x = *(const uint32_t*)r0;
        af.y = *(const uint32_t*)r1;
        af.z = *(const uint32_t*)(r0+8);
        af.w = *(const uint32_t*)(r1+8);
#pragma unroll
        for (int nt=0;nt<3;nt++){
            uint2 bf = __ldg(g_TYBHh + (kk*3+nt)*32 + lane);
            mma_f16(c[nt][0],c[nt][1],c[nt][2],c[nt][3], af, bf);
        }
    }
    float2* Fy2 = (float2*)g_Fy;
    int o = mt*16+g;
#pragma unroll
    for (int nt=0;nt<3;nt++){
        int ky = nt*4+t4;
        size_t base = (((size_t)(b*MM+ky)*CH + o)<<8) + xr;
        Fy2[base]          = make_float2(c[nt][0], c[nt][1]);
        Fy2[base + (8<<8)] = make_float2(c[nt][2], c[nt][3]);
    }
}

// ---------------- constant prep ----------------
__global__ void k_frw(const float* __restrict__ pw_w, const float* __restrict__ fc1w){
    int t = blockIdx.x*blockDim.x + threadIdx.x;
    if (t < 16384){                                  // pw fp16 B-frags
        int layer = t>>12; int d = t&4095;
        int kk=d>>10, ot=(d>>7)&7, lane=(d>>2)&31, kh=(d>>1)&1, hi=d&1;
        int t4=lane&3, g=lane>>2;
        int k = kk*16 + kh*8 + t4*2 + hi;
        int o = ot*8 + g;
        ((unsigned short*)g_PWFh)[t] = h_us(pw_w[(layer*CH+o)*CH + k]);
    } else if (t < 24576){                           // fc1 fp16 B-frags
        int d = t - 16384;
        int kk=d>>11, ot=(d>>7)&15, lane=(d>>2)&31, kh=(d>>1)&1, hi=d&1;
        int t4=lane&3, g=lane>>2;
        int k = kk*16 + kh*8 + t4*2 + hi;
        int f = ot*8 + g;
        ((unsigned short*)g_FC1Fh)[d] = h_us(fc1w[f*CH + k]);
    } else if (t < 32768){                           // TYinv fp16 A-frags (+zero pad)
        int u = t - 24576;
        int hi=u&1, r=(u>>1)&3, lane=(u>>3)&31, yt=(u>>8)&15, kk=u>>12;
        int kh=r>>1, hf=r&1, g=lane>>2, t4=lane&3;
        int y = yt*16 + g + 8*hf;
        int relk = kk*16 + kh*8 + t4*2 + hi;
        float v = 0.f;
        if (relk < 24){
            int ky2 = relk>>1;
            int r2 = (ky2*y) & 255;
            double s2,c2; sincospi(2.0*r2/256.0, &s2, &c2);
            if ((relk&1)==0) v = (ky2==0)? 1.0f : 2.0f*(float)c2;
            else             v = (ky2==0)? 0.0f : -2.0f*(float)s2;
        }
        ((unsigned short*)g_TYFh)[u] = h_us(v);
    } else if (t < 38912){                           // fwd y-DFT fp16 B-frags
        int u = t - 32768;
        int hi = u&1, kh=(u>>1)&1, lane=(u>>2)&31;
        int nt = (u>>7)%3, kk = u/384;
        int t4=lane&3, g=lane>>2;
        int y = kk*16 + kh*8 + t4*2 + hi;
        int n = nt*8 + g;
        int kmode = n>>1;
        int rr = (kmode*y)&255;
        double s,c; sincospi(2.0*rr/256.0, &s, &c);
        float v = (n&1)? (float)(-s) : (float)c;
        ((unsigned short*)g_TYBHh)[(((kk*3+nt)*32+lane)*2+kh)*2+hi] = h_us(v);
    } else if (t < 63488){                           // fwd x-DFT fp16 A-frags (24576)
        int u = t - 38912;
        int hi=u&1, r=(u>>1)&3, lane=(u>>3)&31;
        int mt=(u>>8)%3, kk=u/768;
        int kh=r>>1, hf=r&1, g=lane>>2, t4=lane&3;
        int m = mt*16 + g + 8*hf;
        int k = kk*16 + kh*8 + t4*2 + hi;
        int j = m>>1, ri = m&1;
        int x = k>>1, xi = k&1;
        int keff = (j<12)? j : (j-24);
        int rr = ((keff*x)%256 + 256) & 255;
        double s,c; sincospi(2.0*rr/256.0, &s, &c);
        float v = (ri==0) ? ((xi==0)? (float)c : (float)s)
                          : ((xi==0)? (float)(-s) : (float)c);
        ((unsigned short*)g_F1Ah)[u] = h_us(v);
    } else if (t < 88064){                           // inv x-DFT tf32 B-frags
        int u = t - 63488;
        int kh = u&1, lane = (u>>1)&31, nt = (u>>6)&63, kk = u>>12;
        int g = lane>>2, t4 = lane&3;
        int k = kk*8 + t4 + 4*kh;
        int j = k>>1, ri = k&1;
        int n = nt*8 + g;
        int x = n>>1, xi = n&1;
        int keff = (j<12)? j : (j-24);
        int rr = ((keff*x)%256 + 256) & 255;
        double s,c; sincospi(2.0*rr/256.0, &s, &c);
        float v = (ri==0) ? ((xi==0)? (float)c : (float)s)
                          : ((xi==0)? (float)(-s) : (float)c);
        g_F2B[u] = f2tf32(v * (1.0f/65536.0f));
    }
}

// ---------------- weight transpose via smem ----------------
#define WMIX_SMEM (2*64*145*4)
__global__ void __launch_bounds__(256) k_wmix(const float* __restrict__ w1,
                                              const float* __restrict__ w2){
    extern __shared__ float sm[];
    float* sre = sm;
    float* sim = sm + 64*145;
    int which = blockIdx.x & 1;
    int li = blockIdx.x >> 1;
    const float2* src = ((const float2*)(which? w2 : w1)) + (size_t)li*9216;
    for (int t=threadIdx.x; t<9216; t+=256){
        float2 v = src[t];
        int o = t/144, jk = t - o*144;
        sre[o*145+jk] = v.x;
        sim[o*145+jk] = v.y;
    }
    __syncthreads();
    int l = li>>6, i = li&63;
    int warp = threadIdx.x>>5, lane = threadIdx.x&31;
    for (int jk=warp; jk<144; jk+=8){
        int jm = jk/12, ky = jk - jm*12;
        int j = jm + (which? 12:0);
        float2* dst = ((float2*)g_WMIX) + ((size_t)((l*12+ky)*24 + j))*4096 + i*64;
        dst[lane]    = make_float2(sre[lane*145+jk],      sim[lane*145+jk]);
        dst[lane+32] = make_float2(sre[(lane+32)*145+jk], sim[(lane+32)*145+jk]);
    }
}

// ---------------- lift (fc0) -> Fy (fp16 tile + fp16 epi) ----------------
#define LIFT_SMEM ((8448 + 256)*4)
__global__ void __launch_bounds__(256) k_lift_fy(const float* __restrict__ x,
                                                 const float* __restrict__ fw,
                                                 const float* __restrict__ fb){
    extern __shared__ float smf[];
    __half* HSh = (__half*)smf;             // [64][PADHh]
    float* xs = smf + 8448;
    int b = blockIdx.x>>8, xr = blockIdx.x&255;
    int tid = threadIdx.x;
    if (tid < 64)
        ((float4*)xs)[tid] = ((const float4*)(x + (((size_t)b)<<16) + (xr<<8)))[tid];
    __syncthreads();
    float gx = xr*(1.0f/255.0f);
    for (int t=tid; t<CH*64; t+=256){
        int i=t>>6, q=t&63;
        float w0=__ldg(fw+i*3), w1=__ldg(fw+i*3+1), w2=__ldg(fw+i*3+2);
        float base = w1*gx + __ldg(fb+i);
        float v0 = w0*xs[q*4  ] + w2*((q*4  )*(1.0f/255.0f)) + base;
        float v1 = w0*xs[q*4+1] + w2*((q*4+1)*(1.0f/255.0f)) + base;
        float v2 = w0*xs[q*4+2] + w2*((q*4+2)*(1.0f/255.0f)) + base;
        float v3 = w0*xs[q*4+3] + w2*((q*4+3)*(1.0f/255.0f)) + base;
        *(__half2*)&HSh[i*PADHh + q*4]     = __floats2half2_rn(v0, v1);
        *(__half2*)&HSh[i*PADHh + q*4 + 2] = __floats2half2_rn(v2, v3);
    }
    __syncthreads();
    if (tid < 128) dft_epi_h(HSh, b, xr, tid>>5, tid&31);
}

// ---------------- K-spec: fp16 GEMM1 (in-kernel pack) + mix + tf32 GEMM2 ----------------
#define G_STRIDE 65
#define G_F (48*G_STRIDE)
#define AF2_F (6*4*32*4)
#define PB1_F (48*128)
#define BF1H_F 16384
#define SPEC_SMEM ((BF1H_F + G_F + AF2_F + PB1_F)*4)

__global__ void __launch_bounds__(512,1)
k_spec(int layer){
    extern __shared__ float sm[];
    uint2* BF1h = (uint2*)sm;            // 8192 uint2 (64KB)
    float* Gs   = sm + BF1H_F;
    float* AF2  = Gs + G_F;
    float* PB   = AF2 + AF2_F;
    int b = blockIdx.x/12, ky = blockIdx.x%12;
    int tid = threadIdx.x, lane = tid&31, warp = tid>>5;

    // pack Fy -> fp16 B-frags (k = 2x+ri, n = channel c)
    const float2* fy = ((const float2*)g_Fy) + (((size_t)(b*MM+ky))<<14);
    for (int t=tid; t<64*256; t+=512){
        int c = t>>8, x = t&255;
        float2 v = fy[t];
        int nt = c>>3;
        int laneb = ((c&7)<<2) | (x&3);
        int kk = x>>3, kh = (x>>2)&1;
        ((uint32_t*)BF1h)[(((kk*8+nt)*32) + laneb)*2 + kh] = h2_u32(v.x, v.y);
    }
    __syncthreads();

    {   // GEMM1 fp16 split-k: 48 units, dual 8-deep chains each
        for (int u=warp; u<48; u+=16){
            int tile = u%24, khalf = u/24;
            int mt = tile%3, nt = tile/3;
            float c0=0.f,c1=0.f,c2=0.f,c3=0.f;
            float d0=0.f,d1=0.f,d2=0.f,d3=0.f;
            int kb = khalf*16;
#pragma unroll
            for (int kk=kb; kk<kb+8; kk++){
                uint4 a0 = __ldg(g_F1Ah + (kk*3+mt)*32 + lane);
                uint2 b0 = BF1h[(kk*8+nt)*32 + lane];
                uint4 a1 = __ldg(g_F1Ah + ((kk+8)*3+mt)*32 + lane);
                uint2 b1 = BF1h[((kk+8)*8+nt)*32 + lane];
                mma_f16(c0,c1,c2,c3, a0, b0);
                mma_f16(d0,d1,d2,d3, a1, b1);
            }
            float* pb = PB + u*128 + lane*4;
            pb[0]=c0+d0; pb[1]=c1+d1; pb[2]=c2+d2; pb[3]=c3+d3;
        }
    }
    __syncthreads();
    for (int t=tid; t<3072; t+=512){
        int row = t>>6, col = t&63;
        int mt = row>>4, rr = row&15, g = rr&7, hi = rr>>3;
        int nt = col>>3, cc = col&7, t4 = cc>>1, r0 = (hi<<1)|(cc&1);
        int lidx = g*4+t4;
        int tile = nt*3+mt;
        Gs[row*G_STRIDE+col] = PB[tile*128 + lidx*4 + r0] + PB[(tile+24)*128 + lidx*4 + r0];
    }
    __syncthreads();
    {   // mode mix (fp32 scalar)
        const float2* WM = ((const float2*)g_WMIX) + ((size_t)((layer*12+ky)*24))*4096;
#pragma unroll
        for (int r=0; r<3; r++){
            int item = tid + 512*r;
            int j = item>>6, o = item&63;
            const float2* wrow = WM + j*4096 + o;
            const float* Gr = Gs + (2*j)*G_STRIDE;
            const float* Gi = Gs + (2*j+1)*G_STRIDE;
            float ar0=0.f, ai0=0.f, ar1=0.f, ai1=0.f;
#pragma unroll 8
            for (int i=0;i<64;i+=2){
                float2 wv0 = __ldg(wrow + i*64);
                float2 wv1 = __ldg(wrow + (i+1)*64);
                float g0r = Gr[i],   g0i = Gi[i];
                float g1r = Gr[i+1], g1i = Gi[i+1];
                ar0 += g0r*wv0.x - g0i*wv0.y;
                ai0 += g0r*wv0.y + g0i*wv0.x;
                ar1 += g1r*wv1.x - g1i*wv1.y;
                ai1 += g1r*wv1.y + g1i*wv1.x;
            }
            float ar = ar0+ar1, ai = ai0+ai1;
            int mt=o>>4, half=(o>>3)&1, gg=o&7;
            int k0=2*j;
            int kk=k0>>3, t40=k0&3, kh=(k0>>2)&1;
            int base = ((kk*4+mt)<<5);
            AF2[(base + ((gg<<2)|t40    ))*4 + ((kh<<1)|half)] = f2tf32(ar);
            AF2[(base + ((gg<<2)|(t40+1)))*4 + ((kh<<1)|half)] = f2tf32(ai);
        }
    }
    __syncthreads();
    {   // GEMM2 tf32 -> E
        int mt = warp&3, ntb = (warp>>2)<<4;
        float4 Areg[6];
#pragma unroll
        for (int kk=0;kk<6;kk++)
            Areg[kk] = ((const float4*)AF2)[((kk*4+mt)<<5)+lane];
        int g=lane>>2, t4=lane&3;
        const float2* B2 = (const float2*)g_F2B;
        float2* E2 = (float2*)g_E;
        for (int ni=0;ni<16;ni++){
            int nt = ntb+ni;
            float c0=0.f,c1=0.f,c2=0.f,c3=0.f;
#pragma unroll
            for (int kk=0;kk<6;kk++){
                float2 bf = __ldg(B2 + ((kk*64+nt)<<5)+lane);
                mma_tf32(c0,c1,c2,c3, Areg[kk].x,Areg[kk].y,Areg[kk].z,Areg[kk].w, bf.x,bf.y);
            }
            int x = nt*4+t4, o = mt*16+g;
            E2[((size_t)(b*HH+x)*CH + o  )*12 + ky] = make_float2(c0,c1);
            E2[((size_t)(b*HH+x)*CH + o+8)*12 + ky] = make_float2(c2,c3);
        }
    }
}

// ---------------- K5: fused layer (fp16 GEMMs + fp16 HSh + fp16 epi) ----------------
#define K5_SMEM (18240*4)

__global__ void __launch_bounds__(256,2)
k_layer(const float* __restrict__ xg, const float* __restrict__ fc0w,
        const float* __restrict__ fc0b, const float* __restrict__ pw_b,
        const float* __restrict__ fc1b, const float* __restrict__ fc2w,
        const float* __restrict__ fc2b, float* __restrict__ out, int layer){
    extern __shared__ float smf[];
    uint4* AFh = (uint4*)smf;               // 2048 uint4
    uint2* EF  = (uint2*)(smf + 8192);      // 512 uint2
    float* part= smf + 8192;                // head overlay
    __half* HSh = (__half*)(smf + 9216);    // [64][PADHh]
    float* bs  = smf + 17664;
    float* w0s = bs + 64;
    float* b0s = w0s + 192;
    float* xs  = b0s + 64;
    int b = blockIdx.x>>8, xr = blockIdx.x&255;
    int tid = threadIdx.x, lane = tid&31, warp = tid>>5;

    for (int t=tid; t<1024; t+=256) ((uint32_t*)EF)[t] = 0;
    if (tid<64) bs[tid] = pw_b[layer*CH+tid];
    if (layer==0){
        if (tid<192) w0s[tid] = fc0w[tid];
        if (tid<64)  b0s[tid] = fc0b[tid];
        if (tid<64)
            ((float4*)xs)[tid] = ((const float4*)(xg + (((size_t)b)<<16)+(xr<<8)))[tid];
    }
    __syncthreads();

    {   // E scatter -> fp16 B-frags
        const float* Eb = g_E + ((size_t)(b*HH+xr))*CH*24;
        unsigned short* EFh = (unsigned short*)EF;
        for (int t=tid; t<KXM*CH; t+=256){
            int o=t/24, ke=t%24;
            int kk=ke>>4, kin=ke&15, t4e=(kin>>1)&3, hi=kin&1, kh=kin>>3;
            int ot=o>>3, g=o&7;
            EFh[(((kk*8+ot)*32 + (g*4+t4e))*2 + kh)*2 + hi] = h_us(Eb[t]);
        }
    }
    if (layer==0){
        float gx = xr*(1.0f/255.0f);
        for (int t=tid; t<CH*64; t+=256){
            int i=t>>6, q=t&63;
            float w0=w0s[i*3], w1=w0s[i*3+1], w2=w0s[i*3+2];
            float base = w1*gx + b0s[i];
            float v0 = w0*xs[q*4  ] + w2*((q*4  )*(1.0f/255.0f)) + base;
            float v1 = w0*xs[q*4+1] + w2*((q*4+1)*(1.0f/255.0f)) + base;
            float v2 = w0*xs[q*4+2] + w2*((q*4+2)*(1.0f/255.0f)) + base;
            float v3 = w0*xs[q*4+3] + w2*((q*4+3)*(1.0f/255.0f)) + base;
            *(__half2*)&HSh[i*PADHh + q*4]     = __floats2half2_rn(v0, v1);
            *(__half2*)&HSh[i*PADHh + q*4 + 2] = __floats2half2_rn(v2, v3);
        }
        __syncthreads();
        for (int u=tid; u<2048; u+=256) pack_row_h(HSh, AFh, u);
    } else {
        const uint4* hg = g_h4 + ((size_t)blockIdx.x<<11);
        for (int t=tid; t<2048; t+=256) AFh[t] = hg[t];
    }
    __syncthreads();

    int wy = warp>>1, wo = warp&1;
    float c[4][4][4];
#pragma unroll
    for (int mi=0;mi<4;mi++)
#pragma unroll
        for (int ni=0;ni<4;ni++)
#pragma unroll
            for (int r=0;r<4;r++) c[mi][ni][r]=0.f;

    const uint2* PW = g_PWFh + layer*1024;
#pragma unroll
    for (int kk=0; kk<4; kk++){
        uint2 bf[4];
#pragma unroll
        for (int ni=0;ni<4;ni++)
            bf[ni] = __ldg(PW + (kk*8 + wo*4+ni)*32 + lane);
#pragma unroll
        for (int mi=0;mi<4;mi++){
            uint4 af = AFh[(kk*16 + wy*4+mi)*32 + lane];
#pragma unroll
            for (int ni=0;ni<4;ni++)
                mma_f16(c[mi][ni][0],c[mi][ni][1],c[mi][ni][2],c[mi][ni][3], af, bf[ni]);
        }
    }
#pragma unroll
    for (int kk=0; kk<2; kk++){
        uint2 bf[4];
#pragma unroll
        for (int ni=0;ni<4;ni++)
            bf[ni] = EF[(kk*8 + wo*4+ni)*32 + lane];
#pragma unroll
        for (int mi=0;mi<4;mi++){
            uint4 af = __ldg(g_TYFh + (kk*16 + wy*4+mi)*32 + lane);
#pragma unroll
            for (int ni=0;ni<4;ni++)
                mma_f16(c[mi][ni][0],c[mi][ni][1],c[mi][ni][2],c[mi][ni][3], af, bf[ni]);
        }
    }

    int g = lane>>2, t4 = lane&3;
    int dogelu = (layer < NLAYERS-1);
#pragma unroll
    for (int mi=0;mi<4;mi++){
#pragma unroll
        for (int ni=0;ni<4;ni++){
            int o = (wo*4+ni)*8 + 2*t4;
            float bb0 = bs[o], bb1 = bs[o+1];
            float v0 = c[mi][ni][0] + bb0;
            float v1 = c[mi][ni][1] + bb1;
            float v2 = c[mi][ni][2] + bb0;
            float v3 = c[mi][ni][3] + bb1;
            if (dogelu){ v0=gelu_f(v0); v1=gelu_f(v1); v2=gelu_f(v2); v3=gelu_f(v3); }
            c[mi][ni][0]=v0; c[mi][ni][1]=v1; c[mi][ni][2]=v2; c[mi][ni][3]=v3;
        }
    }

    if (layer < NLAYERS-1){
        __syncthreads();
#pragma unroll
        for (int mi=0;mi<4;mi++){
            int y = (wy*4+mi)*16 + g;
#pragma unroll
            for (int ni=0;ni<4;ni++){
                int o = (wo*4+ni)*8 + 2*t4;
                HSh[ o   *PADHh + y  ] = __float2half_rn(c[mi][ni][0]);
                HSh[(o+1)*PADHh + y  ] = __float2half_rn(c[mi][ni][1]);
                HSh[ o   *PADHh + y+8] = __float2half_rn(c[mi][ni][2]);
                HSh[(o+1)*PADHh + y+8] = __float2half_rn(c[mi][ni][3]);
            }
        }
        __syncthreads();
        if (warp < 4){
            dft_epi_h(HSh, b, xr, warp, lane);
        } else {
            uint4* hg = g_h4 + ((size_t)blockIdx.x<<11);
            for (int u=tid-128; u<2048; u+=128) pack_row_h(HSh, hg, u);
        }
        return;
    }

    // ---- layer 3: fused head (fp16) ----
    __syncthreads();
    {
        unsigned short* AH = (unsigned short*)AFh;
#pragma unroll
        for (int mi=0;mi<4;mi++){
#pragma unroll
            for (int ni=0;ni<4;ni++){
#pragma unroll
                for (int r=0;r<4;r++){
                    int o = (wo*4+ni)*8 + 2*t4 + (r&1);
                    int y = (wy*4+mi)*16 + g + ((r>>1)<<3);
                    int kk=o>>4, kin=o&15, t4n=(kin>>1)&3, hin=kin&1, khn=kin>>3;
                    int yt=y>>4, yin=y&15, gn=yin&7, halfn=yin>>3;
                    int reg = khn*2 + halfn;
                    AH[(((kk*16+yt)*32 + (gn*4+t4n))*4 + reg)*2 + hin] =
                        h_us(c[mi][ni][r]);
                }
            }
        }
    }
    __syncthreads();

    float s0[4] = {0.f,0.f,0.f,0.f}, s1[4] = {0.f,0.f,0.f,0.f};
#pragma unroll
    for (int p=0; p<2; p++){
#pragma unroll
        for (int mi=0;mi<4;mi++)
#pragma unroll
            for (int ni=0;ni<4;ni++)
#pragma unroll
                for (int r=0;r<4;r++) c[mi][ni][r]=0.f;
#pragma unroll
        for (int kk=0; kk<4; kk++){
            uint2 bf[4];
#pragma unroll
            for (int ni=0;ni<4;ni++)
                bf[ni] = __ldg(g_FC1Fh + (kk*16 + p*8 + wo*4+ni)*32 + lane);
#pragma unroll
            for (int mi=0;mi<4;mi++){
                uint4 af = AFh[(kk*16 + wy*4+mi)*32 + lane];
#pragma unroll
                for (int ni=0;ni<4;ni++)
                    mma_f16(c[mi][ni][0],c[mi][ni][1],c[mi][ni][2],c[mi][ni][3],
                            af, bf[ni]);
            }
        }
#pragma unroll
        for (int mi=0;mi<4;mi++){
#pragma unroll
            for (int ni=0;ni<4;ni++){
                int f = (p*8 + wo*4+ni)*8 + 2*t4;
                float ba = __ldg(fc1b+f), bb = __ldg(fc1b+f+1);
                float wa = __ldg(fc2w+f), wb = __ldg(fc2w+f+1);
                s0[mi] += gelu_f(c[mi][ni][0]+ba)*wa + gelu_f(c[mi][ni][1]+bb)*wb;
                s1[mi] += gelu_f(c[mi][ni][2]+ba)*wa + gelu_f(c[mi][ni][3]+bb)*wb;
            }
        }
    }
#pragma unroll
    for (int mi=0;mi<4;mi++){
        float a0 = s0[mi], a1 = s1[mi];
        a0 += __shfl_xor_sync(0xffffffffu, a0, 1);
        a0 += __shfl_xor_sync(0xffffffffu, a0, 2);
        a1 += __shfl_xor_sync(0xffffffffu, a1, 1);
        a1 += __shfl_xor_sync(0xffffffffu, a1, 2);
        if (t4==0){
            int y = (wy*4+mi)*16 + g;
            part[wo*WW + y]   = a0;
            part[wo*WW + y+8] = a1;
        }
    }
    __syncthreads();
    {
        int y = tid;
        float s = part[y] + part[WW+y] + __ldg(fc2b);
        out[(((size_t)b)<<16) + (xr<<8) + y] = s;
    }
}

// ---------------- launch ----------------
extern "C" void kernel_launch(void* const* d_in, const int* in_sizes, int n_in,
                              void* d_out, int out_size){
    (void)in_sizes; (void)n_in; (void)out_size;
    const float* x     = (const float*)d_in[0];
    const float* fc0_w = (const float*)d_in[1];
    const float* fc0_b = (const float*)d_in[2];
    const float* w1    = (const float*)d_in[3];
    const float* w2    = (const float*)d_in[4];
    const float* pw_w  = (const float*)d_in[5];
    const float* pw_b  = (const float*)d_in[6];
    const float* fc1_w = (const float*)d_in[7];
    const float* fc1_b = (const float*)d_in[8];
    const float* fc2_w = (const float*)d_in[9];
    const float* fc2_b = (const float*)d_in[10];
    float* out = (float*)d_out;

    cudaFuncSetAttribute(k_layer,   cudaFuncAttributeMaxDynamicSharedMemorySize, K5_SMEM);
    cudaFuncSetAttribute(k_spec,    cudaFuncAttributeMaxDynamicSharedMemorySize, SPEC_SMEM);
    cudaFuncSetAttribute(k_lift_fy, cudaFuncAttributeMaxDynamicSharedMemorySize, LIFT_SMEM);
    cudaFuncSetAttribute(k_wmix,    cudaFuncAttributeMaxDynamicSharedMemorySize, WMIX_SMEM);

    k_frw<<<344,256>>>(pw_w, fc1_w);
    k_wmix<<<512,256,WMIX_SMEM>>>(w1, w2);
    k_lift_fy<<<BATCH*HH,256,LIFT_SMEM>>>(x, fc0_w, fc0_b);
    for (int l=0; l<NLAYERS; l++){
        k_spec<<<BATCH*MM,512,SPEC_SMEM>>>(l);
        k_layer<<<BATCH*HH,256,K5_SMEM>>>(x, fc0_w, fc0_b, pw_b,
                                          fc1_b, fc2_w, fc2_b, out, l);
    }
}

// round 17
// speedup vs baseline: 1.3104x; 1.2588x over previous
#include <cuda_runtime.h>
#include <cuda_fp16.h>
#include <cstdint>
#include <cstddef>

#define BATCH 8
#define CH 64
#define HH 256
#define WW 256
#define MM 12
#define KXM 24
#define NLAYERS 4
#define FCH 128
#define PADHh 264

// ---------------- device scratch ----------------
__device__ uint4 g_h4[BATCH*HH*HH*8];          // fp16 A-frag image, 2048 uint4/block
__device__ uint4 g_FyH4[BATCH*MM*4096];        // Fy fp16 B-frag image per (b,ky)
__device__ uint32_t g_EFh[BATCH*HH*1024];      // E fp16 B-frag image per (b,x); pad stays 0
// fp16 fragment tables (m16n8k16)
__device__ uint2 g_PWFh[NLAYERS*1024];         // pw B-frags
__device__ uint2 g_FC1Fh[2048];                // fc1 B-frags
__device__ uint4 g_TYFh[1024];                 // TYinv A-frags (pad k>=24 -> 0)
__device__ uint2 g_TYBHh[16*3*32];             // fwd y-DFT B-frags (fp16)
__device__ uint4 g_F1Ah[3072];                 // fwd x-DFT A-frags (fp16, M=48,K=512)
// tf32 tables (k_spec tail)
__device__ float g_F2B[6*64*32*2];             // B-frags inv x-DFT (/65536)
__device__ float g_WMIX[NLAYERS*MM*KXM*CH*CH*2];

__device__ __forceinline__ float gelu_f(float v){
    float z = fabsf(v)*0.70710678118654752f;
    float t = __fdividef(1.0f, fmaf(0.3275911f, z, 1.0f));
    float p = fmaf(1.061405429f, t, -1.453152027f);
    p = fmaf(p, t, 1.421413741f);
    p = fmaf(p, t, -0.284496736f);
    p = fmaf(p, t, 0.254829592f);
    p *= t;
    float e = __expf(-z*z);
    return v * (0.5f*(1.0f + copysignf(fmaf(-p, e, 1.0f), v)));
}
__device__ __forceinline__ float f2tf32(float x){
    uint32_t r; asm("cvt.rna.tf32.f32 %0, %1;" : "=r"(r) : "f"(x));
    return __uint_as_float(r);
}
__device__ __forceinline__ void mma_tf32(float& d0,float& d1,float& d2,float& d3,
                                         float a0,float a1,float a2,float a3,
                                         float b0,float b1){
    asm volatile("mma.sync.aligned.m16n8k8.row.col.f32.tf32.tf32.f32 "
        "{%0,%1,%2,%3}, {%4,%5,%6,%7}, {%8,%9}, {%0,%1,%2,%3};"
        : "+f"(d0),"+f"(d1),"+f"(d2),"+f"(d3)
        : "r"(__float_as_uint(a0)),"r"(__float_as_uint(a1)),
          "r"(__float_as_uint(a2)),"r"(__float_as_uint(a3)),
          "r"(__float_as_uint(b0)),"r"(__float_as_uint(b1)));
}
__device__ __forceinline__ void mma_f16(float& d0,float& d1,float& d2,float& d3,
                                        uint4 a, uint2 b){
    asm volatile("mma.sync.aligned.m16n8k16.row.col.f32.f16.f16.f32 "
        "{%0,%1,%2,%3}, {%4,%5,%6,%7}, {%8,%9}, {%0,%1,%2,%3};"
        : "+f"(d0),"+f"(d1),"+f"(d2),"+f"(d3)
        : "r"(a.x),"r"(a.y),"r"(a.z),"r"(a.w),"r"(b.x),"r"(b.y));
}
__device__ __forceinline__ unsigned short h_us(float v){
    __half h = __float2half_rn(v);
    return *(unsigned short*)&h;
}
__device__ __forceinline__ uint32_t h2_u32(float a, float b){
    __half2 h = __floats2half2_rn(a, b);
    return *(uint32_t*)&h;
}

// pack fp16 HSh tile [k=i][y] -> fp16 A-frag image item u (0..2047)
__device__ __forceinline__ void pack_row_h(const __half* __restrict__ HSh,
                                           uint4* __restrict__ dst, int u){
    int row=u>>5, lane=u&31;
    int kk=row>>4, yt=row&15, g=lane>>2, t4=lane&3;
    uint32_t w[4];
#pragma unroll
    for (int r=0;r<4;r++){
        int kh=r>>1, hf=r&1;
        int y = yt*16 + g + 8*hf;
        int k0 = kk*16 + kh*8 + t4*2;
        __half2 hh = __halves2half2(HSh[k0*PADHh+y], HSh[(k0+1)*PADHh+y]);
        w[r] = *(uint32_t*)&hh;
    }
    dst[u] = make_uint4(w[0],w[1],w[2],w[3]);
}

// ---------------- fused y-DFT epilogue -> Fy fp16 fragment image ----------------
__device__ __forceinline__ void dft_epi_h(const __half* __restrict__ HSh, int b, int xr,
                                          int warp, int lane){
    int g = lane>>2, t4 = lane&3;
    int mt = warp;
    float c[3][4];
#pragma unroll
    for (int nt=0;nt<3;nt++)
#pragma unroll
        for (int r=0;r<4;r++) c[nt][r]=0.f;
#pragma unroll
    for (int kk=0; kk<16; kk++){
        const __half* r0 = HSh + (mt*16+g)*PADHh + kk*16 + t4*2;
        const __half* r1 = r0 + 8*PADHh;
        uint4 af;
        af.x = *(const uint32_t*)r0;
        af.y = *(const uint32_t*)r1;
        af.z = *(const uint32_t*)(r0+8);
        af.w = *(const uint32_t*)(r1+8);
#pragma unroll
        for (int nt=0;nt<3;nt++){
            uint2 bf = __ldg(g_TYBHh + (kk*3+nt)*32 + lane);
            mma_f16(c[nt][0],c[nt][1],c[nt][2],c[nt][3], af, bf);
        }
    }
    // direct store into per-(b,ky) Fy fragment image: k=2x+ri, n=channel
    int kkx = xr>>3, khx = (xr>>2)&1;
    int laneb = (g<<2) | (xr&3);
#pragma unroll
    for (int nt=0;nt<3;nt++){
        int ky = nt*4+t4;
        uint32_t* im32 = (uint32_t*)(g_FyH4 + (size_t)(b*MM+ky)*4096);
        im32[((kkx*8 + mt*2  )*32 + laneb)*2 + khx] = h2_u32(c[nt][0], c[nt][1]);
        im32[((kkx*8 + mt*2+1)*32 + laneb)*2 + khx] = h2_u32(c[nt][2], c[nt][3]);
    }
}

// ---------------- constant prep ----------------
__global__ void k_frw(const float* __restrict__ pw_w, const float* __restrict__ fc1w){
    int t = blockIdx.x*blockDim.x + threadIdx.x;
    if (t < 16384){                                  // pw fp16 B-frags
        int layer = t>>12; int d = t&4095;
        int kk=d>>10, ot=(d>>7)&7, lane=(d>>2)&31, kh=(d>>1)&1, hi=d&1;
        int t4=lane&3, g=lane>>2;
        int k = kk*16 + kh*8 + t4*2 + hi;
        int o = ot*8 + g;
        ((unsigned short*)g_PWFh)[t] = h_us(pw_w[(layer*CH+o)*CH + k]);
    } else if (t < 24576){                           // fc1 fp16 B-frags
        int d = t - 16384;
        int kk=d>>11, ot=(d>>7)&15, lane=(d>>2)&31, kh=(d>>1)&1, hi=d&1;
        int t4=lane&3, g=lane>>2;
        int k = kk*16 + kh*8 + t4*2 + hi;
        int f = ot*8 + g;
        ((unsigned short*)g_FC1Fh)[d] = h_us(fc1w[f*CH + k]);
    } else if (t < 32768){                           // TYinv fp16 A-frags (+zero pad)
        int u = t - 24576;
        int hi=u&1, r=(u>>1)&3, lane=(u>>3)&31, yt=(u>>8)&15, kk=u>>12;
        int kh=r>>1, hf=r&1, g=lane>>2, t4=lane&3;
        int y = yt*16 + g + 8*hf;
        int relk = kk*16 + kh*8 + t4*2 + hi;
        float v = 0.f;
        if (relk < 24){
            int ky2 = relk>>1;
            int r2 = (ky2*y) & 255;
            double s2,c2; sincospi(2.0*r2/256.0, &s2, &c2);
            if ((relk&1)==0) v = (ky2==0)? 1.0f : 2.0f*(float)c2;
            else             v = (ky2==0)? 0.0f : -2.0f*(float)s2;
        }
        ((unsigned short*)g_TYFh)[u] = h_us(v);
    } else if (t < 38912){                           // fwd y-DFT fp16 B-frags
        int u = t - 32768;
        int hi = u&1, kh=(u>>1)&1, lane=(u>>2)&31;
        int nt = (u>>7)%3, kk = u/384;
        int t4=lane&3, g=lane>>2;
        int y = kk*16 + kh*8 + t4*2 + hi;
        int n = nt*8 + g;
        int kmode = n>>1;
        int rr = (kmode*y)&255;
        double s,c; sincospi(2.0*rr/256.0, &s, &c);
        float v = (n&1)? (float)(-s) : (float)c;
        ((unsigned short*)g_TYBHh)[(((kk*3+nt)*32+lane)*2+kh)*2+hi] = h_us(v);
    } else if (t < 63488){                           // fwd x-DFT fp16 A-frags (24576)
        int u = t - 38912;
        int hi=u&1, r=(u>>1)&3, lane=(u>>3)&31;
        int mt=(u>>8)%3, kk=u/768;
        int kh=r>>1, hf=r&1, g=lane>>2, t4=lane&3;
        int m = mt*16 + g + 8*hf;
        int k = kk*16 + kh*8 + t4*2 + hi;
        int j = m>>1, ri = m&1;
        int x = k>>1, xi = k&1;
        int keff = (j<12)? j : (j-24);
        int rr = ((keff*x)%256 + 256) & 255;
        double s,c; sincospi(2.0*rr/256.0, &s, &c);
        float v = (ri==0) ? ((xi==0)? (float)c : (float)s)
                          : ((xi==0)? (float)(-s) : (float)c);
        ((unsigned short*)g_F1Ah)[u] = h_us(v);
    } else if (t < 88064){                           // inv x-DFT tf32 B-frags
        int u = t - 63488;
        int kh = u&1, lane = (u>>1)&31, nt = (u>>6)&63, kk = u>>12;
        int g = lane>>2, t4 = lane&3;
        int k = kk*8 + t4 + 4*kh;
        int j = k>>1, ri = k&1;
        int n = nt*8 + g;
        int x = n>>1, xi = n&1;
        int keff = (j<12)? j : (j-24);
        int rr = ((keff*x)%256 + 256) & 255;
        double s,c; sincospi(2.0*rr/256.0, &s, &c);
        float v = (ri==0) ? ((xi==0)? (float)c : (float)s)
                          : ((xi==0)? (float)(-s) : (float)c);
        g_F2B[u] = f2tf32(v * (1.0f/65536.0f));
    }
}

// ---------------- weight transpose via smem ----------------
#define WMIX_SMEM (2*64*145*4)
__global__ void __launch_bounds__(256) k_wmix(const float* __restrict__ w1,
                                              const float* __restrict__ w2){
    extern __shared__ float sm[];
    float* sre = sm;
    float* sim = sm + 64*145;
    int which = blockIdx.x & 1;
    int li = blockIdx.x >> 1;
    const float2* src = ((const float2*)(which? w2 : w1)) + (size_t)li*9216;
    for (int t=threadIdx.x; t<9216; t+=256){
        float2 v = src[t];
        int o = t/144, jk = t - o*144;
        sre[o*145+jk] = v.x;
        sim[o*145+jk] = v.y;
    }
    __syncthreads();
    int l = li>>6, i = li&63;
    int warp = threadIdx.x>>5, lane = threadIdx.x&31;
    for (int jk=warp; jk<144; jk+=8){
        int jm = jk/12, ky = jk - jm*12;
        int j = jm + (which? 12:0);
        float2* dst = ((float2*)g_WMIX) + ((size_t)((l*12+ky)*24 + j))*4096 + i*64;
        dst[lane]    = make_float2(sre[lane*145+jk],      sim[lane*145+jk]);
        dst[lane+32] = make_float2(sre[(lane+32)*145+jk], sim[(lane+32)*145+jk]);
    }
}

// ---------------- lift (fc0) -> Fy fragment image ----------------
#define LIFT_SMEM ((8448 + 256)*4)
__global__ void __launch_bounds__(256) k_lift_fy(const float* __restrict__ x,
                                                 const float* __restrict__ fw,
                                                 const float* __restrict__ fb){
    extern __shared__ float smf[];
    __half* HSh = (__half*)smf;             // [64][PADHh]
    float* xs = smf + 8448;
    int b = blockIdx.x>>8, xr = blockIdx.x&255;
    int tid = threadIdx.x;
    if (tid < 64)
        ((float4*)xs)[tid] = ((const float4*)(x + (((size_t)b)<<16) + (xr<<8)))[tid];
    __syncthreads();
    float gx = xr*(1.0f/255.0f);
    for (int t=tid; t<CH*64; t+=256){
        int i=t>>6, q=t&63;
        float w0=__ldg(fw+i*3), w1=__ldg(fw+i*3+1), w2=__ldg(fw+i*3+2);
        float base = w1*gx + __ldg(fb+i);
        float v0 = w0*xs[q*4  ] + w2*((q*4  )*(1.0f/255.0f)) + base;
        float v1 = w0*xs[q*4+1] + w2*((q*4+1)*(1.0f/255.0f)) + base;
        float v2 = w0*xs[q*4+2] + w2*((q*4+2)*(1.0f/255.0f)) + base;
        float v3 = w0*xs[q*4+3] + w2*((q*4+3)*(1.0f/255.0f)) + base;
        *(__half2*)&HSh[i*PADHh + q*4]     = __floats2half2_rn(v0, v1);
        *(__half2*)&HSh[i*PADHh + q*4 + 2] = __floats2half2_rn(v2, v3);
    }
    __syncthreads();
    if (tid < 128) dft_epi_h(HSh, b, xr, tid>>5, tid&31);
}

// ---------------- K-spec: fp16 GEMM1 + mix + tf32 GEMM2 -> E frag image ----------------
#define G_STRIDE 65
#define G_F (48*G_STRIDE)
#define AF2_F (6*4*32*4)
#define PB1_F (48*128)
#define BF1H_F 16384
#define SPEC_SMEM ((BF1H_F + G_F + AF2_F + PB1_F)*4)

__global__ void __launch_bounds__(512,1)
k_spec(int layer){
    extern __shared__ float sm[];
    uint4* BF1h = (uint4*)sm;            // 4096 uint4 (64KB)
    float* Gs   = sm + BF1H_F;
    float* AF2  = Gs + G_F;
    float* PB   = AF2 + AF2_F;
    int b = blockIdx.x/12, ky = blockIdx.x%12;
    int tid = threadIdx.x, lane = tid&31, warp = tid>>5;

    {   // copy Fy fragment image (already packed by epilogue)
        const uint4* src = g_FyH4 + (size_t)(b*MM+ky)*4096;
        for (int t=tid; t<4096; t+=512) BF1h[t] = __ldg(src+t);
    }
    __syncthreads();

    {   // GEMM1 fp16 split-k: 48 units, dual 8-deep chains each
        const uint2* B2 = (const uint2*)BF1h;
        for (int u=warp; u<48; u+=16){
            int tile = u%24, khalf = u/24;
            int mt = tile%3, nt = tile/3;
            float c0=0.f,c1=0.f,c2=0.f,c3=0.f;
            float d0=0.f,d1=0.f,d2=0.f,d3=0.f;
            int kb = khalf*16;
#pragma unroll
            for (int kk=kb; kk<kb+8; kk++){
                uint4 a0 = __ldg(g_F1Ah + (kk*3+mt)*32 + lane);
                uint2 b0 = B2[(kk*8+nt)*32 + lane];
                uint4 a1 = __ldg(g_F1Ah + ((kk+8)*3+mt)*32 + lane);
                uint2 b1 = B2[((kk+8)*8+nt)*32 + lane];
                mma_f16(c0,c1,c2,c3, a0, b0);
                mma_f16(d0,d1,d2,d3, a1, b1);
            }
            float* pb = PB + u*128 + lane*4;
            pb[0]=c0+d0; pb[1]=c1+d1; pb[2]=c2+d2; pb[3]=c3+d3;
        }
    }
    __syncthreads();
    for (int t=tid; t<3072; t+=512){
        int row = t>>6, col = t&63;
        int mt = row>>4, rr = row&15, g = rr&7, hi = rr>>3;
        int nt = col>>3, cc = col&7, t4 = cc>>1, r0 = (hi<<1)|(cc&1);
        int lidx = g*4+t4;
        int tile = nt*3+mt;
        Gs[row*G_STRIDE+col] = PB[tile*128 + lidx*4 + r0] + PB[(tile+24)*128 + lidx*4 + r0];
    }
    __syncthreads();
    {   // mode mix (fp32 scalar)
        const float2* WM = ((const float2*)g_WMIX) + ((size_t)((layer*12+ky)*24))*4096;
#pragma unroll
        for (int r=0; r<3; r++){
            int item = tid + 512*r;
            int j = item>>6, o = item&63;
            const float2* wrow = WM + j*4096 + o;
            const float* Gr = Gs + (2*j)*G_STRIDE;
            const float* Gi = Gs + (2*j+1)*G_STRIDE;
            float ar0=0.f, ai0=0.f, ar1=0.f, ai1=0.f;
#pragma unroll 8
            for (int i=0;i<64;i+=2){
                float2 wv0 = __ldg(wrow + i*64);
                float2 wv1 = __ldg(wrow + (i+1)*64);
                float g0r = Gr[i],   g0i = Gi[i];
                float g1r = Gr[i+1], g1i = Gi[i+1];
                ar0 += g0r*wv0.x - g0i*wv0.y;
                ai0 += g0r*wv0.y + g0i*wv0.x;
                ar1 += g1r*wv1.x - g1i*wv1.y;
                ai1 += g1r*wv1.y + g1i*wv1.x;
            }
            float ar = ar0+ar1, ai = ai0+ai1;
            int mt=o>>4, half=(o>>3)&1, gg=o&7;
            int k0=2*j;
            int kk=k0>>3, t40=k0&3, kh=(k0>>2)&1;
            int base = ((kk*4+mt)<<5);
            AF2[(base + ((gg<<2)|t40    ))*4 + ((kh<<1)|half)] = f2tf32(ar);
            AF2[(base + ((gg<<2)|(t40+1)))*4 + ((kh<<1)|half)] = f2tf32(ai);
        }
    }
    __syncthreads();
    {   // GEMM2 tf32 -> E fragment image (fp16 direct store)
        int mt = warp&3, ntb = (warp>>2)<<4;
        float4 Areg[6];
#pragma unroll
        for (int kk=0;kk<6;kk++)
            Areg[kk] = ((const float4*)AF2)[((kk*4+mt)<<5)+lane];
        int g=lane>>2, t4=lane&3;
        int kkE = (ky>=8)?1:0, khE=(ky&7)>>2;
        int lm = g*4 + (ky&3);
        for (int ni=0;ni<16;ni++){
            int nt = ntb+ni;
            float c0=0.f,c1=0.f,c2=0.f,c3=0.f;
#pragma unroll
            for (int kk=0;kk<6;kk++){
                float2 bf = __ldg(((const float2*)g_F2B) + ((kk*64+nt)<<5)+lane);
                mma_tf32(c0,c1,c2,c3, Areg[kk].x,Areg[kk].y,Areg[kk].z,Areg[kk].w, bf.x,bf.y);
            }
            int x = nt*4+t4;
            uint32_t* img = g_EFh + (size_t)(b*HH+x)*1024;
            img[((kkE*8 + mt*2  )*32 + lm)*2 + khE] = h2_u32(c0,c1);
            img[((kkE*8 + mt*2+1)*32 + lm)*2 + khE] = h2_u32(c2,c3);
        }
    }
}

// ---------------- K5: fused layer (fp16 GEMMs, direct-frag A and E) ----------------
#define K5_SMEM (18240*4)

__global__ void __launch_bounds__(256,2)
k_layer(const float* __restrict__ xg, const float* __restrict__ fc0w,
        const float* __restrict__ fc0b, const float* __restrict__ pw_b,
        const float* __restrict__ fc1b, const float* __restrict__ fc2w,
        const float* __restrict__ fc2b, float* __restrict__ out, int layer){
    extern __shared__ float smf[];
    uint4* AFh = (uint4*)smf;               // 2048 uint4 (layer0 stage / layer3 head)
    uint2* EF  = (uint2*)(smf + 8192);      // 512 uint2
    float* part= smf + 8192;                // head overlay
    __half* HSh = (__half*)(smf + 9216);    // [64][PADHh]
    float* bs  = smf + 17664;
    float* w0s = bs + 64;
    float* b0s = w0s + 192;
    float* xs  = b0s + 64;
    int b = blockIdx.x>>8, xr = blockIdx.x&255;
    int tid = threadIdx.x, lane = tid&31, warp = tid>>5;
    const uint4* Ag = g_h4 + ((size_t)blockIdx.x<<11);

    // EF: straight copy of pre-packed fragment image (incl. zero pad)
    ((uint4*)EF)[tid] = __ldg((const uint4*)(g_EFh + (size_t)(b*HH+xr)*1024) + tid);
    if (tid<64) bs[tid] = pw_b[layer*CH+tid];
    if (layer==0){
        if (tid<192) w0s[tid] = fc0w[tid];
        if (tid<64)  b0s[tid] = fc0b[tid];
        if (tid<64)
            ((float4*)xs)[tid] = ((const float4*)(xg + (((size_t)b)<<16)+(xr<<8)))[tid];
        __syncthreads();
        float gx = xr*(1.0f/255.0f);
        for (int t=tid; t<CH*64; t+=256){
            int i=t>>6, q=t&63;
            float w0=w0s[i*3], w1=w0s[i*3+1], w2=w0s[i*3+2];
            float base = w1*gx + b0s[i];
            float v0 = w0*xs[q*4  ] + w2*((q*4  )*(1.0f/255.0f)) + base;
            float v1 = w0*xs[q*4+1] + w2*((q*4+1)*(1.0f/255.0f)) + base;
            float v2 = w0*xs[q*4+2] + w2*((q*4+2)*(1.0f/255.0f)) + base;
            float v3 = w0*xs[q*4+3] + w2*((q*4+3)*(1.0f/255.0f)) + base;
            *(__half2*)&HSh[i*PADHh + q*4]     = __floats2half2_rn(v0, v1);
            *(__half2*)&HSh[i*PADHh + q*4 + 2] = __floats2half2_rn(v2, v3);
        }
        __syncthreads();
        for (int u=tid; u<2048; u+=256) pack_row_h(HSh, AFh, u);
    }
    __syncthreads();

    int wy = warp>>1, wo = warp&1;
    float c[4][4][4];
#pragma unroll
    for (int mi=0;mi<4;mi++)
#pragma unroll
        for (int ni=0;ni<4;ni++)
#pragma unroll
            for (int r=0;r<4;r++) c[mi][ni][r]=0.f;

    const uint2* PW = g_PWFh + layer*1024;
#pragma unroll
    for (int kk=0; kk<4; kk++){
        uint2 bf[4];
#pragma unroll
        for (int ni=0;ni<4;ni++)
            bf[ni] = __ldg(PW + (kk*8 + wo*4+ni)*32 + lane);
#pragma unroll
        for (int mi=0;mi<4;mi++){
            int idx = (kk*16 + wy*4+mi)*32 + lane;
            uint4 af = (layer==0) ? AFh[idx] : __ldg(Ag + idx);
#pragma unroll
            for (int ni=0;ni<4;ni++)
                mma_f16(c[mi][ni][0],c[mi][ni][1],c[mi][ni][2],c[mi][ni][3], af, bf[ni]);
        }
    }
#pragma unroll
    for (int kk=0; kk<2; kk++){
        uint2 bf[4];
#pragma unroll
        for (int ni=0;ni<4;ni++)
            bf[ni] = EF[(kk*8 + wo*4+ni)*32 + lane];
#pragma unroll
        for (int mi=0;mi<4;mi++){
            uint4 af = __ldg(g_TYFh + (kk*16 + wy*4+mi)*32 + lane);
#pragma unroll
            for (int ni=0;ni<4;ni++)
                mma_f16(c[mi][ni][0],c[mi][ni][1],c[mi][ni][2],c[mi][ni][3], af, bf[ni]);
        }
    }

    int g = lane>>2, t4 = lane&3;
    int dogelu = (layer < NLAYERS-1);
#pragma unroll
    for (int mi=0;mi<4;mi++){
#pragma unroll
        for (int ni=0;ni<4;ni++){
            int o = (wo*4+ni)*8 + 2*t4;
            float bb0 = bs[o], bb1 = bs[o+1];
            float v0 = c[mi][ni][0] + bb0;
            float v1 = c[mi][ni][1] + bb1;
            float v2 = c[mi][ni][2] + bb0;
            float v3 = c[mi][ni][3] + bb1;
            if (dogelu){ v0=gelu_f(v0); v1=gelu_f(v1); v2=gelu_f(v2); v3=gelu_f(v3); }
            c[mi][ni][0]=v0; c[mi][ni][1]=v1; c[mi][ni][2]=v2; c[mi][ni][3]=v3;
        }
    }

    if (layer < NLAYERS-1){
        __syncthreads();
#pragma unroll
        for (int mi=0;mi<4;mi++){
            int y = (wy*4+mi)*16 + g;
#pragma unroll
            for (int ni=0;ni<4;ni++){
                int o = (wo*4+ni)*8 + 2*t4;
                HSh[ o   *PADHh + y  ] = __float2half_rn(c[mi][ni][0]);
                HSh[(o+1)*PADHh + y  ] = __float2half_rn(c[mi][ni][1]);
                HSh[ o   *PADHh + y+8] = __float2half_rn(c[mi][ni][2]);
                HSh[(o+1)*PADHh + y+8] = __float2half_rn(c[mi][ni][3]);
            }
        }
        __syncthreads();
        if (warp < 4){
            dft_epi_h(HSh, b, xr, warp, lane);
        } else {
            uint4* hg = g_h4 + ((size_t)blockIdx.x<<11);
            for (int u=tid-128; u<2048; u+=128) pack_row_h(HSh, hg, u);
        }
        return;
    }

    // ---- layer 3: fused head (fp16) ----
    __syncthreads();
    {
        unsigned short* AH = (unsigned short*)AFh;
#pragma unroll
        for (int mi=0;mi<4;mi++){
#pragma unroll
            for (int ni=0;ni<4;ni++){
#pragma unroll
                for (int r=0;r<4;r++){
                    int o = (wo*4+ni)*8 + 2*t4 + (r&1);
                    int y = (wy*4+mi)*16 + g + ((r>>1)<<3);
                    int kk=o>>4, kin=o&15, t4n=(kin>>1)&3, hin=kin&1, khn=kin>>3;
                    int yt=y>>4, yin=y&15, gn=yin&7, halfn=yin>>3;
                    int reg = khn*2 + halfn;
                    AH[(((kk*16+yt)*32 + (gn*4+t4n))*4 + reg)*2 + hin] =
                        h_us(c[mi][ni][r]);
                }
            }
        }
    }
    __syncthreads();

    float s0[4] = {0.f,0.f,0.f,0.f}, s1[4] = {0.f,0.f,0.f,0.f};
#pragma unroll
    for (int p=0; p<2; p++){
#pragma unroll
        for (int mi=0;mi<4;mi++)
#pragma unroll
            for (int ni=0;ni<4;ni++)
#pragma unroll
                for (int r=0;r<4;r++) c[mi][ni][r]=0.f;
#pragma unroll
        for (int kk=0; kk<4; kk++){
            uint2 bf[4];
#pragma unroll
            for (int ni=0;ni<4;ni++)
                bf[ni] = __ldg(g_FC1Fh + (kk*16 + p*8 + wo*4+ni)*32 + lane);
#pragma unroll
            for (int mi=0;mi<4;mi++){
                uint4 af = AFh[(kk*16 + wy*4+mi)*32 + lane];
#pragma unroll
                for (int ni=0;ni<4;ni++)
                    mma_f16(c[mi][ni][0],c[mi][ni][1],c[mi][ni][2],c[mi][ni][3],
                            af, bf[ni]);
            }
        }
#pragma unroll
        for (int mi=0;mi<4;mi++){
#pragma unroll
            for (int ni=0;ni<4;ni++){
                int f = (p*8 + wo*4+ni)*8 + 2*t4;
                float ba = __ldg(fc1b+f), bb = __ldg(fc1b+f+1);
                float wa = __ldg(fc2w+f), wb = __ldg(fc2w+f+1);
                s0[mi] += gelu_f(c[mi][ni][0]+ba)*wa + gelu_f(c[mi][ni][1]+bb)*wb;
                s1[mi] += gelu_f(c[mi][ni][2]+ba)*wa + gelu_f(c[mi][ni][3]+bb)*wb;
            }
        }
    }
#pragma unroll
    for (int mi=0;mi<4;mi++){
        float a0 = s0[mi], a1 = s1[mi];
        a0 += __shfl_xor_sync(0xffffffffu, a0, 1);
        a0 += __shfl_xor_sync(0xffffffffu, a0, 2);
        a1 += __shfl_xor_sync(0xffffffffu, a1, 1);
        a1 += __shfl_xor_sync(0xffffffffu, a1, 2);
        if (t4==0){
            int y = (wy*4+mi)*16 + g;
            part[wo*WW + y]   = a0;
            part[wo*WW + y+8] = a1;
        }
    }
    __syncthreads();
    {
        int y = tid;
        float s = part[y] + part[WW+y] + __ldg(fc2b);
        out[(((size_t)b)<<16) + (xr<<8) + y] = s;
    }
}

// ---------------- launch ----------------
extern "C" void kernel_launch(void* const* d_in, const int* in_sizes, int n_in,
                              void* d_out, int out_size){
    (void)in_sizes; (void)n_in; (void)out_size;
    const float* x     = (const float*)d_in[0];
    const float* fc0_w = (const float*)d_in[1];
    const float* fc0_b = (const float*)d_in[2];
    const float* w1    = (const float*)d_in[3];
    const float* w2    = (const float*)d_in[4];
    const float* pw_w  = (const float*)d_in[5];
    const float* pw_b  = (const float*)d_in[6];
    const float* fc1_w = (const float*)d_in[7];
    const float* fc1_b = (const float*)d_in[8];
    const float* fc2_w = (const float*)d_in[9];
    const float* fc2_b = (const float*)d_in[10];
    float* out = (float*)d_out;

    cudaFuncSetAttribute(k_layer,   cudaFuncAttributeMaxDynamicSharedMemorySize, K5_SMEM);
    cudaFuncSetAttribute(k_spec,    cudaFuncAttributeMaxDynamicSharedMemorySize, SPEC_SMEM);
    cudaFuncSetAttribute(k_lift_fy, cudaFuncAttributeMaxDynamicSharedMemorySize, LIFT_SMEM);
    cudaFuncSetAttribute(k_wmix,    cudaFuncAttributeMaxDynamicSharedMemorySize, WMIX_SMEM);

    k_frw<<<344,256>>>(pw_w, fc1_w);
    k_wmix<<<512,256,WMIX_SMEM>>>(w1, w2);
    k_lift_fy<<<BATCH*HH,256,LIFT_SMEM>>>(x, fc0_w, fc0_b);
    for (int l=0; l<NLAYERS; l++){
        k_spec<<<BATCH*MM,512,SPEC_SMEM>>>(l);
        k_layer<<<BATCH*HH,256,K5_SMEM>>>(x, fc0_w, fc0_b, pw_b,
                                          fc1_b, fc2_w, fc2_b, out, l);
    }
}